// round 1
// baseline (speedup 1.0000x reference)
#include <cuda_runtime.h>
#include <cuda_bf16.h>

// AdderConvReLUBlock: out = relu(-Σ_{ci,ky,kx} |xp - w|).
// Every accumulated term is >= 0, so the pre-ReLU value is <= 0 everywhere,
// and relu() maps it to exactly 0. The reference output is identically zero;
// the optimal kernel is a pure 8 MB zero-fill of d_out (HBM-write bound).

__global__ void AdderConvReLUBlock_8693013807225_kernel(float4* __restrict__ out4,
                                                        int n4,
                                                        float* __restrict__ out_tail,
                                                        int tail_start,
                                                        int n_total) {
    const float4 z = make_float4(0.0f, 0.0f, 0.0f, 0.0f);
    int idx = blockIdx.x * blockDim.x + threadIdx.x;
    int stride = gridDim.x * blockDim.x;
    for (int i = idx; i < n4; i += stride) {
        out4[i] = z;
    }
    // Scalar tail (out_size is 2^21 so this never fires, kept for robustness).
    int t = tail_start + idx;
    if (t < n_total) {
        out_tail[t] = 0.0f;
    }
}

extern "C" void kernel_launch(void* const* d_in, const int* in_sizes, int n_in,
                              void* d_out, int out_size) {
    (void)d_in; (void)in_sizes; (void)n_in;

    float* out = (float*)d_out;
    int n4 = out_size >> 2;          // number of float4 stores
    int tail_start = n4 << 2;        // first element not covered by float4 path

    const int threads = 256;
    int blocks = (n4 + threads - 1) / threads;
    if (blocks > 2048) blocks = 2048;   // grid-stride covers the rest
    if (blocks < 1) blocks = 1;

    AdderConvReLUBlock_8693013807225_kernel<<<blocks, threads>>>(
        (float4*)d_out, n4, out, tail_start, out_size);
}